// round 16
// baseline (speedup 1.0000x reference)
#include <cuda_runtime.h>
#include <cuda_fp16.h>
#include <cstdint>

#define BB   4
#define TT   2048
#define DIN  768
#define DOUT 768
#define NH   12
#define HD   64
#define MROWS (BB*TT)   // 8192
#define QKVSZ (BB*NH*TT*HD)

// ---------------------------------------------------------------------------
// Scratch (static device memory -- no allocations allowed)
// ---------------------------------------------------------------------------
__device__ __half g_xh  [MROWS*DIN];       // x -> fp16
__device__ __half g_QKV [3*QKVSZ];         // Q|K|V, [b,h,t,hd]; Q scaled by 0.125*log2e
__device__ __half g_ctx [MROWS*DOUT];      // [b,t,d]
__device__ __half g_Wh  [DIN*3*DOUT];      // [k][ Wq | Wk | Wv ] row-major fp16
__device__ __half g_WoH [DOUT*DOUT];       // Wo row-major fp16

// ---------------------------------------------------------------------------
// PTX helpers (baseline sm_75/80-class; harness targets compute_103, no 'a')
// ---------------------------------------------------------------------------
__device__ __forceinline__ uint32_t smem_u32(const void* p) {
    uint32_t a;
    asm("{ .reg .u64 t; cvta.to.shared.u64 t, %1; cvt.u32.u64 %0, t; }"
        : "=r"(a) : "l"(p));
    return a;
}

#define CP_ASYNC16(dst, src) \
    asm volatile("cp.async.cg.shared.global [%0], [%1], 16;" \
                 :: "r"(dst), "l"(src) : "memory")
#define CP_COMMIT() asm volatile("cp.async.commit_group;" ::: "memory")
#define CP_WAIT1()  asm volatile("cp.async.wait_group 1;" ::: "memory")
#define CP_WAIT0()  asm volatile("cp.async.wait_group 0;" ::: "memory")

__device__ __forceinline__ void ldsm4(uint32_t r[4], uint32_t addr) {
    asm volatile("ldmatrix.sync.aligned.m8n8.x4.shared.b16 {%0,%1,%2,%3}, [%4];"
        : "=r"(r[0]), "=r"(r[1]), "=r"(r[2]), "=r"(r[3]) : "r"(addr));
}
__device__ __forceinline__ void ldsm4t(uint32_t r[4], uint32_t addr) {
    asm volatile("ldmatrix.sync.aligned.m8n8.x4.trans.shared.b16 {%0,%1,%2,%3}, [%4];"
        : "=r"(r[0]), "=r"(r[1]), "=r"(r[2]), "=r"(r[3]) : "r"(addr));
}

// fp32-accumulator MMA (GEMMs, PV, l)
__device__ __forceinline__ void mma_f16(float c[4], const uint32_t a[4],
                                        uint32_t b0, uint32_t b1) {
    asm volatile(
        "mma.sync.aligned.m16n8k16.row.col.f32.f16.f16.f32 "
        "{%0,%1,%2,%3}, {%4,%5,%6,%7}, {%8,%9}, {%0,%1,%2,%3};"
        : "+f"(c[0]), "+f"(c[1]), "+f"(c[2]), "+f"(c[3])
        : "r"(a[0]), "r"(a[1]), "r"(a[2]), "r"(a[3]), "r"(b0), "r"(b1));
}

// fp16-accumulator MMA (flash S only). C frags = packed half2 pairs.
__device__ __forceinline__ void mma_f16c16(uint32_t c[2], const uint32_t a[4],
                                           uint32_t b0, uint32_t b1) {
    asm volatile(
        "mma.sync.aligned.m16n8k16.row.col.f16.f16.f16.f16 "
        "{%0,%1}, {%2,%3,%4,%5}, {%6,%7}, {%0,%1};"
        : "+r"(c[0]), "+r"(c[1])
        : "r"(a[0]), "r"(a[1]), "r"(a[2]), "r"(a[3]), "r"(b0), "r"(b1));
}

__device__ __forceinline__ uint32_t packh2(float x, float y) {
    __half2 h = __floats2half2_rn(x, y);
    return *reinterpret_cast<uint32_t*>(&h);
}
__device__ __forceinline__ uint32_t h2ex2(uint32_t x) {
    uint32_t r;
    asm("ex2.approx.f16x2 %0, %1;" : "=r"(r) : "r"(x));
    return r;
}
__device__ __forceinline__ uint32_t hadd2u(uint32_t a, uint32_t b) {
    __half2 r = __hadd2(*reinterpret_cast<const __half2*>(&a),
                        *reinterpret_cast<const __half2*>(&b));
    return *reinterpret_cast<uint32_t*>(&r);
}

// ---------------------------------------------------------------------------
// Merged preprocessing: flat grid converts x and all 4 weights to fp16.
// ---------------------------------------------------------------------------
#define XB (MROWS * DIN / 1024)     // 6144 blocks for x
#define WB (DIN * DOUT / 1024)      // 576 blocks per weight

__global__ __launch_bounds__(256)
void preproc(const float* __restrict__ x,
             const float* __restrict__ Wq, const float* __restrict__ Wk,
             const float* __restrict__ Wv, const float* __restrict__ Wo,
             __half* __restrict__ xh, __half* __restrict__ Wh,
             __half* __restrict__ WoH)
{
    const int b = blockIdx.x;
    if (b < XB) {
        const size_t i = ((size_t)b * 256 + threadIdx.x) * 4;
        float4 v = *(const float4*)(x + i);
        uint2 u;
        u.x = packh2(v.x, v.y);
        u.y = packh2(v.z, v.w);
        *(uint2*)(xh + i) = u;
    } else {
        const int w = b - XB;
        const int z = w / WB;                       // 0..3
        const int r = w % WB;
        const float* src = (z == 0) ? Wq : (z == 1) ? Wk : (z == 2) ? Wv : Wo;
        const size_t i = ((size_t)r * 256 + threadIdx.x) * 4;
        float4 v = *(const float4*)(src + i);
        uint2 u;
        u.x = packh2(v.x, v.y);
        u.y = packh2(v.z, v.w);
        if (z < 3) {
            const int k = (int)(i / DOUT), n = (int)(i % DOUT);
            *(uint2*)(Wh + (size_t)k * (3 * DOUT) + z * DOUT + n) = u;
        } else {
            *(uint2*)(WoH + i) = u;
        }
    }
}

// ---------------------------------------------------------------------------
// Pipelined fp16 mma.sync GEMM v3: C[128 x 64] tile = A @ W.
// 128 threads (4 warps, 2(M) x 2(N)), warp tile 64x32, acc 64 fp32 regs,
// 4 CTAs/SM. Double-buffered cp.async (BK=64). B rows stride 72 (pad 8).
// EPI 0: fp32 + bias (final). EPI 1: fp16 head-split QKV (Q scaled).
// ---------------------------------------------------------------------------
template<int EPI>
__global__ __launch_bounds__(128, 4)
void gemm_h(const __half* __restrict__ A, const __half* __restrict__ W,
            const float* __restrict__ bias, void* __restrict__ Cv,
            int Kd, int lda, int ldb, int ldc)
{
    constexpr int LDA_ = 72;
    constexpr int LDB_ = 72;                 // 64 halfs + 8 pad
    constexpr int ASZ  = 128 * LDA_;
    constexpr int BSZ  = 64 * LDB_;

    extern __shared__ __half smh[];
    __half* As = smh;
    __half* Bs = smh + 2 * ASZ;
    const uint32_t sbA = smem_u32(As);
    const uint32_t sbB = smem_u32(Bs);

    const int tid  = threadIdx.x;            // 0..127
    const int wid  = tid >> 5;               // 0..3
    const int lane = tid & 31;
    const int gidx = lane >> 2;
    const int ctig = lane & 3;
    const int bn = blockIdx.x * 64;
    const int bm = blockIdx.y * 128;

    const int warp_n = (wid & 1) * 32;       // 2 warps along N (32 cols each)
    const int warp_m = (wid >> 1) * 64;      // 2 warps along M (64 rows each)

    float acc[4][4][4];                      // mf x n8 x quad = 64 regs
#pragma unroll
    for (int mf = 0; mf < 4; mf++)
#pragma unroll
        for (int nf = 0; nf < 4; nf++)
#pragma unroll
            for (int q = 0; q < 4; q++) acc[mf][nf][q] = 0.f;

    const int nk = Kd >> 6;                  // BK = 64

    auto issue = [&](int it, int buf) {
        const int kt = it << 6;
#pragma unroll
        for (int j = 0; j < 8; j++) {        // A: 128 rows x 8 chunks = 1024
            const int seg = j * 128 + tid;
            const int r = seg >> 3, c = seg & 7;
            CP_ASYNC16(sbA + (uint32_t)(buf * ASZ + r * LDA_ + c * 8) * 2,
                       A + (size_t)(bm + r) * lda + kt + c * 8);
        }
#pragma unroll
        for (int j = 0; j < 4; j++) {        // B: 64 k-rows x 8 chunks = 512
            const int seg = j * 128 + tid;
            const int r = seg >> 3, c = seg & 7;
            CP_ASYNC16(sbB + (uint32_t)(buf * BSZ + r * LDB_ + c * 8) * 2,
                       W + (size_t)(kt + r) * ldb + bn + c * 8);
        }
        CP_COMMIT();
    };

    issue(0, 0);

    const int arow = lane & 15;
    const int acol = (lane >> 4) << 3;
    const int vrow = ((lane >> 3) & 1) * 8 + (lane & 7);
    const int vcol = (lane >> 4) << 3;

    for (int i = 0; i < nk; i++) {
        const int buf = i & 1;
        if (i + 1 < nk) { issue(i + 1, buf ^ 1); CP_WAIT1(); }
        else            { CP_WAIT0(); }
        __syncthreads();

        const uint32_t Ab = sbA + (uint32_t)(buf * ASZ) * 2;
        const uint32_t Bb = sbB + (uint32_t)(buf * BSZ) * 2;

#pragma unroll
        for (int ks = 0; ks < 4; ks++) {
            uint32_t afr[4][4];
#pragma unroll
            for (int mf = 0; mf < 4; mf++)
                ldsm4(afr[mf], Ab + (uint32_t)((warp_m + mf * 16 + arow) * LDA_
                                               + ks * 16 + acol) * 2);
#pragma unroll
            for (int np = 0; np < 2; np++) { // 32 cols = 2 x 16
                uint32_t bfr[4];
                ldsm4t(bfr, Bb + (uint32_t)((ks * 16 + vrow) * LDB_
                                            + warp_n + np * 16 + vcol) * 2);
#pragma unroll
                for (int mf = 0; mf < 4; mf++) {
                    mma_f16(acc[mf][2 * np],     afr[mf], bfr[0], bfr[1]);
                    mma_f16(acc[mf][2 * np + 1], afr[mf], bfr[2], bfr[3]);
                }
            }
        }
        __syncthreads();
    }

#pragma unroll
    for (int mf = 0; mf < 4; mf++) {
#pragma unroll
        for (int nf = 0; nf < 4; nf++) {
            const int row0 = bm + warp_m + mf * 16 + gidx;
            const int cl   = warp_n + nf * 8 + ctig * 2;
            if (EPI == 1) {
                __half* C = (__half*)Cv;
                const int mat = bn / DOUT;
                const float sc = (mat == 0) ? 0.125f * 1.44269504f : 1.f;
                const int cg  = bn + cl - mat * DOUT;
                const int h_  = cg >> 6, hd_ = cg & 63;
                const int b_  = row0 >> 11, t_ = row0 & (TT - 1);
                __half* d0 = C + (size_t)mat * QKVSZ
                           + (((size_t)(b_ * NH + h_) << 11) + t_) * HD + hd_;
                __half* d1 = d0 + 8 * HD;
                *(uint32_t*)d0 = packh2(acc[mf][nf][0] * sc, acc[mf][nf][1] * sc);
                *(uint32_t*)d1 = packh2(acc[mf][nf][2] * sc, acc[mf][nf][3] * sc);
            } else {
                float* C = (float*)Cv;
                float* d0 = C + (size_t)row0 * ldc + bn + cl;
                float* d1 = d0 + (size_t)8 * ldc;
                float b0 = 0.f, b1 = 0.f;
                if (bias) { b0 = bias[bn + cl]; b1 = bias[bn + cl + 1]; }
                *(float2*)d0 = make_float2(acc[mf][nf][0] + b0, acc[mf][nf][1] + b1);
                *(float2*)d1 = make_float2(acc[mf][nf][2] + b0, acc[mf][nf][3] + b1);
            }
        }
    }
}

// ---------------------------------------------------------------------------
// Fused flash attention v9 (R15 form, locked): 128 threads, 32 q-rows/warp,
// fp16-accum S, in-place ex2, single ones-MMA per mf for l (pre-summed via
// shallow HADD2 on the fma pipe), 3-stage cp.async, 1 barrier per key block.
// ---------------------------------------------------------------------------
__global__ __launch_bounds__(128, 3)
void flash_attn(const __half* __restrict__ Q, const __half* __restrict__ K,
                const __half* __restrict__ V, __half* __restrict__ ctx)
{
    constexpr int LDH = 72;
    constexpr int QSZ = 128 * LDH;
    constexpr int KSZ = 64 * LDH;
    constexpr uint32_t ONES = 0x3C003C00u;  // half2(1, 1)

    extern __shared__ __half smh[];
    __half* Qs = smh;                        // 128 x 72
    __half* Ks = smh + QSZ;                  // [3][64][72]
    __half* Vs = Ks + 3 * KSZ;               // [3][64][72]
    const uint32_t sbQ = smem_u32(Qs);
    const uint32_t sbK = smem_u32(Ks);
    const uint32_t sbV = smem_u32(Vs);

    const int tid  = threadIdx.x;            // 0..127
    const int wid  = tid >> 5;               // 0..3
    const int lane = tid & 31;
    const int gidx = lane >> 2;
    const int ctig = lane & 3;
    const int q0 = blockIdx.x * 128;
    const int bh = blockIdx.y;
    const int warp_m = wid * 32;             // 32 q-rows per warp

    const __half* Qb = Q + ((size_t)bh * TT + q0) * HD;
    const __half* Kb = K + (size_t)bh * TT * HD;
    const __half* Vb = V + (size_t)bh * TT * HD;

    // stage Q
#pragma unroll
    for (int j = 0; j < 8; j++) {
        const int seg = j * 128 + tid;
        const int r = seg >> 3, c = seg & 7;
        *(uint4*)(Qs + r * LDH + c * 8) = *(const uint4*)(Qb + r * HD + c * 8);
    }

    const int arow = lane & 15;
    const int acol = (lane >> 4) << 3;
    const int brow = ((lane >> 4) << 3) + (lane & 7);
    const int bcol = ((lane >> 3) & 1) * 8;
    const int vrow = ((lane >> 3) & 1) * 8 + (lane & 7);
    const int vcol = (lane >> 4) << 3;

    auto issueKV = [&](int blk, int buf) {
        const __half* kp = Kb + (size_t)blk * 64 * HD;
        const __half* vp = Vb + (size_t)blk * 64 * HD;
#pragma unroll
        for (int j = 0; j < 4; j++) {
            const int seg = j * 128 + tid;
            const int r = seg >> 3, c = seg & 7;
            CP_ASYNC16(sbK + (uint32_t)(buf * KSZ + r * LDH + c * 8) * 2,
                       kp + r * HD + c * 8);
        }
#pragma unroll
        for (int j = 0; j < 4; j++) {
            const int seg = j * 128 + tid;
            const int r = seg >> 3, c = seg & 7;
            CP_ASYNC16(sbV + (uint32_t)(buf * KSZ + r * LDH + c * 8) * 2,
                       vp + r * HD + c * 8);
        }
        CP_COMMIT();
    };

    issueKV(0, 0);
    issueKV(1, 1);
    __syncthreads();                         // Q staged (overlaps KV issue)

    uint32_t qf[2][4][4];
#pragma unroll
    for (int mf = 0; mf < 2; mf++)
#pragma unroll
        for (int ks = 0; ks < 4; ks++)
            ldsm4(qf[mf][ks], sbQ + (uint32_t)((warp_m + mf * 16 + arow) * LDH
                                               + ks * 16 + acol) * 2);

    float O[2][8][4];
#pragma unroll
    for (int mf = 0; mf < 2; mf++)
#pragma unroll
        for (int nf = 0; nf < 8; nf++)
#pragma unroll
            for (int q = 0; q < 4; q++) O[mf][nf][q] = 0.f;
    float lacc[2][4] = {{0.f, 0.f, 0.f, 0.f}, {0.f, 0.f, 0.f, 0.f}};

    constexpr int NB = TT / 64;              // 32
    int buf = 0;

    for (int i = 0; i < NB; i++) {
        if (i + 1 < NB) CP_WAIT1();
        else            CP_WAIT0();
        __syncthreads();                     // publish stage i; prev compute done

        const uint32_t Kt = sbK + (uint32_t)(buf * KSZ) * 2;
        const uint32_t Vt = sbV + (uint32_t)(buf * KSZ) * 2;

        // ---- S' = (Q * 0.125*log2e) @ K^T, fp16 accum; kf reused by both mf ----
        uint32_t ph[2][8][2];
#pragma unroll
        for (int mf = 0; mf < 2; mf++)
#pragma unroll
            for (int nf = 0; nf < 8; nf++) { ph[mf][nf][0] = 0u; ph[mf][nf][1] = 0u; }

#pragma unroll
        for (int ks = 0; ks < 4; ks++) {
#pragma unroll
            for (int np = 0; np < 4; np++) {
                uint32_t kf[4];
                ldsm4(kf, Kt + (uint32_t)((np * 16 + brow) * LDH + ks * 16 + bcol) * 2);
#pragma unroll
                for (int mf = 0; mf < 2; mf++) {
                    mma_f16c16(ph[mf][2 * np],     qf[mf][ks], kf[0], kf[1]);
                    mma_f16c16(ph[mf][2 * np + 1], qf[mf][ks], kf[2], kf[3]);
                }
            }
        }

        // ---- P = exp2(S') in place ----
#pragma unroll
        for (int mf = 0; mf < 2; mf++)
#pragma unroll
            for (int nf = 0; nf < 8; nf++) {
                ph[mf][nf][0] = h2ex2(ph[mf][nf][0]);
                ph[mf][nf][1] = h2ex2(ph[mf][nf][1]);
            }

        // ---- l: pre-sum P fragments over 4 k-groups, ONE ones-MMA per mf ----
#pragma unroll
        for (int mf = 0; mf < 2; mf++) {
            uint32_t ls[4];
            ls[0] = hadd2u(hadd2u(ph[mf][0][0], ph[mf][2][0]),
                           hadd2u(ph[mf][4][0], ph[mf][6][0]));
            ls[1] = hadd2u(hadd2u(ph[mf][0][1], ph[mf][2][1]),
                           hadd2u(ph[mf][4][1], ph[mf][6][1]));
            ls[2] = hadd2u(hadd2u(ph[mf][1][0], ph[mf][3][0]),
                           hadd2u(ph[mf][5][0], ph[mf][7][0]));
            ls[3] = hadd2u(hadd2u(ph[mf][1][1], ph[mf][3][1]),
                           hadd2u(ph[mf][5][1], ph[mf][7][1]));
            mma_f16(lacc[mf], ls, ONES, ONES);
        }

        // ---- O += P @ V ; vf reused by both mf ----
#pragma unroll
        for (int j = 0; j < 4; j++) {
            uint32_t af[2][4];
#pragma unroll
            for (int mf = 0; mf < 2; mf++) {
                af[mf][0] = ph[mf][2 * j][0];
                af[mf][1] = ph[mf][2 * j][1];
                af[mf][2] = ph[mf][2 * j + 1][0];
                af[mf][3] = ph[mf][2 * j + 1][1];
            }
#pragma unroll
            for (int np = 0; np < 4; np++) {
                uint32_t vf[4];
                ldsm4t(vf, Vt + (uint32_t)((j * 16 + vrow) * LDH + np * 16 + vcol) * 2);
#pragma unroll
                for (int mf = 0; mf < 2; mf++) {
                    mma_f16(O[mf][2 * np],     af[mf], vf[0], vf[1]);
                    mma_f16(O[mf][2 * np + 1], af[mf], vf[2], vf[3]);
                }
            }
        }

        if (i + 2 < NB) issueKV(i + 2, (i + 2) % 3);
        buf = (buf == 2) ? 0 : buf + 1;
    }

    // ---- epilogue ----
    const int b_ = bh / NH, h_ = bh % NH;
#pragma unroll
    for (int mf = 0; mf < 2; mf++) {
        const float i0 = 1.f / lacc[mf][0];
        const float i1 = 1.f / lacc[mf][2];
        const int r0 = q0 + warp_m + mf * 16 + gidx;
        __half* base = ctx + ((size_t)(b_ * TT) + r0) * DOUT + h_ * HD;
#pragma unroll
        for (int nf = 0; nf < 8; nf++) {
            *(uint32_t*)(base + nf * 8 + 2 * ctig) =
                packh2(O[mf][nf][0] * i0, O[mf][nf][1] * i0);
            *(uint32_t*)(base + (size_t)8 * DOUT + nf * 8 + 2 * ctig) =
                packh2(O[mf][nf][2] * i1, O[mf][nf][3] * i1);
        }
    }
}

// ---------------------------------------------------------------------------
extern "C" void kernel_launch(void* const* d_in, const int* in_sizes, int n_in,
                              void* d_out, int out_size)
{
    const float* x  = (const float*)d_in[0];
    const float* Wq = (const float*)d_in[1];
    const float* Wk = (const float*)d_in[2];
    const float* Wv = (const float*)d_in[3];
    const float* Wo = (const float*)d_in[4];
    const float* bo = (const float*)d_in[5];
    float* out = (float*)d_out;

    __half *xh, *QKV, *Cp, *Wh, *WoH;
    cudaGetSymbolAddress((void**)&xh,  g_xh);
    cudaGetSymbolAddress((void**)&QKV, g_QKV);
    cudaGetSymbolAddress((void**)&Cp,  g_ctx);
    cudaGetSymbolAddress((void**)&Wh,  g_Wh);
    cudaGetSymbolAddress((void**)&WoH, g_WoH);

    constexpr int SMGEMM = (2 * 128 * 72 + 2 * 64 * 72) * 2;       // 55296 B
    constexpr int SMFA   = (128 * 72 + 6 * 64 * 72) * 2;           // 73728 B
    cudaFuncSetAttribute(gemm_h<0>, cudaFuncAttributeMaxDynamicSharedMemorySize, SMGEMM);
    cudaFuncSetAttribute(gemm_h<1>, cudaFuncAttributeMaxDynamicSharedMemorySize, SMGEMM);
    cudaFuncSetAttribute(flash_attn, cudaFuncAttributeMaxDynamicSharedMemorySize, SMFA);

    // merged preprocessing (x + all weights, one launch)
    preproc<<<XB + 4 * WB, 256>>>(x, Wq, Wk, Wv, Wo, xh, Wh, WoH);

    // fused QKV projection -> g_QKV [3][b,h,t,hd] fp16 (Q scaled 0.125*log2e)
    gemm_h<1><<<dim3(3 * DOUT / 64, MROWS / 128), 128, SMGEMM>>>(
        xh, Wh, nullptr, QKV, DIN, DIN, 3 * DOUT, 0);

    // fused flash attention -> ctx [b,t,d] fp16
    flash_attn<<<dim3(TT / 128, BB * NH), 128, SMFA>>>(
        QKV, QKV + QKVSZ, QKV + 2 * QKVSZ, Cp);

    // output projection + bias -> fp32 result
    gemm_h<0><<<dim3(DOUT / 64, MROWS / 128), 128, SMGEMM>>>(
        Cp, WoH, bo, out, DOUT, DOUT, DOUT, DOUT);
}

// round 17
// speedup vs baseline: 1.0167x; 1.0167x over previous
#include <cuda_runtime.h>
#include <cuda_fp16.h>
#include <cstdint>

#define BB   4
#define TT   2048
#define DIN  768
#define DOUT 768
#define NH   12
#define HD   64
#define MROWS (BB*TT)   // 8192
#define QKVSZ (BB*NH*TT*HD)

// ---------------------------------------------------------------------------
// Scratch (static device memory -- no allocations allowed)
// ---------------------------------------------------------------------------
__device__ __half g_xh  [MROWS*DIN];       // x -> fp16
__device__ __half g_QKV [3*QKVSZ];         // Q|K|V, [b,h,t,hd]; Q scaled by 0.125*log2e
__device__ __half g_ctx [MROWS*DOUT];      // [b,t,d]
__device__ __half g_Wh  [DIN*3*DOUT];      // [k][ Wq | Wk | Wv ] row-major fp16
__device__ __half g_WoH [DOUT*DOUT];       // Wo row-major fp16

// ---------------------------------------------------------------------------
// PTX helpers (baseline sm_75/80-class; harness targets compute_103, no 'a')
// ---------------------------------------------------------------------------
__device__ __forceinline__ uint32_t smem_u32(const void* p) {
    uint32_t a;
    asm("{ .reg .u64 t; cvta.to.shared.u64 t, %1; cvt.u32.u64 %0, t; }"
        : "=r"(a) : "l"(p));
    return a;
}

#define CP_ASYNC16(dst, src) \
    asm volatile("cp.async.cg.shared.global [%0], [%1], 16;" \
                 :: "r"(dst), "l"(src) : "memory")
#define CP_COMMIT() asm volatile("cp.async.commit_group;" ::: "memory")
#define CP_WAIT1()  asm volatile("cp.async.wait_group 1;" ::: "memory")
#define CP_WAIT0()  asm volatile("cp.async.wait_group 0;" ::: "memory")

__device__ __forceinline__ void ldsm4(uint32_t r[4], uint32_t addr) {
    asm volatile("ldmatrix.sync.aligned.m8n8.x4.shared.b16 {%0,%1,%2,%3}, [%4];"
        : "=r"(r[0]), "=r"(r[1]), "=r"(r[2]), "=r"(r[3]) : "r"(addr));
}
__device__ __forceinline__ void ldsm4t(uint32_t r[4], uint32_t addr) {
    asm volatile("ldmatrix.sync.aligned.m8n8.x4.trans.shared.b16 {%0,%1,%2,%3}, [%4];"
        : "=r"(r[0]), "=r"(r[1]), "=r"(r[2]), "=r"(r[3]) : "r"(addr));
}

// fp32-accumulator MMA (GEMMs, PV, l)
__device__ __forceinline__ void mma_f16(float c[4], const uint32_t a[4],
                                        uint32_t b0, uint32_t b1) {
    asm volatile(
        "mma.sync.aligned.m16n8k16.row.col.f32.f16.f16.f32 "
        "{%0,%1,%2,%3}, {%4,%5,%6,%7}, {%8,%9}, {%0,%1,%2,%3};"
        : "+f"(c[0]), "+f"(c[1]), "+f"(c[2]), "+f"(c[3])
        : "r"(a[0]), "r"(a[1]), "r"(a[2]), "r"(a[3]), "r"(b0), "r"(b1));
}

// fp16-accumulator MMA (flash S only). C frags = packed half2 pairs.
__device__ __forceinline__ void mma_f16c16(uint32_t c[2], const uint32_t a[4],
                                           uint32_t b0, uint32_t b1) {
    asm volatile(
        "mma.sync.aligned.m16n8k16.row.col.f16.f16.f16.f16 "
        "{%0,%1}, {%2,%3,%4,%5}, {%6,%7}, {%0,%1};"
        : "+r"(c[0]), "+r"(c[1])
        : "r"(a[0]), "r"(a[1]), "r"(a[2]), "r"(a[3]), "r"(b0), "r"(b1));
}

__device__ __forceinline__ uint32_t packh2(float x, float y) {
    __half2 h = __floats2half2_rn(x, y);
    return *reinterpret_cast<uint32_t*>(&h);
}
__device__ __forceinline__ uint32_t h2ex2(uint32_t x) {
    uint32_t r;
    asm("ex2.approx.f16x2 %0, %1;" : "=r"(r) : "r"(x));
    return r;
}
__device__ __forceinline__ uint32_t hadd2u(uint32_t a, uint32_t b) {
    __half2 r = __hadd2(*reinterpret_cast<const __half2*>(&a),
                        *reinterpret_cast<const __half2*>(&b));
    return *reinterpret_cast<uint32_t*>(&r);
}

// ---------------------------------------------------------------------------
// Merged preprocessing: flat grid converts x and all 4 weights to fp16.
// ---------------------------------------------------------------------------
#define XB (MROWS * DIN / 1024)     // 6144 blocks for x
#define WB (DIN * DOUT / 1024)      // 576 blocks per weight

__global__ __launch_bounds__(256)
void preproc(const float* __restrict__ x,
             const float* __restrict__ Wq, const float* __restrict__ Wk,
             const float* __restrict__ Wv, const float* __restrict__ Wo,
             __half* __restrict__ xh, __half* __restrict__ Wh,
             __half* __restrict__ WoH)
{
    const int b = blockIdx.x;
    if (b < XB) {
        const size_t i = ((size_t)b * 256 + threadIdx.x) * 4;
        float4 v = *(const float4*)(x + i);
        uint2 u;
        u.x = packh2(v.x, v.y);
        u.y = packh2(v.z, v.w);
        *(uint2*)(xh + i) = u;
    } else {
        const int w = b - XB;
        const int z = w / WB;                       // 0..3
        const int r = w % WB;
        const float* src = (z == 0) ? Wq : (z == 1) ? Wk : (z == 2) ? Wv : Wo;
        const size_t i = ((size_t)r * 256 + threadIdx.x) * 4;
        float4 v = *(const float4*)(src + i);
        uint2 u;
        u.x = packh2(v.x, v.y);
        u.y = packh2(v.z, v.w);
        if (z < 3) {
            const int k = (int)(i / DOUT), n = (int)(i % DOUT);
            *(uint2*)(Wh + (size_t)k * (3 * DOUT) + z * DOUT + n) = u;
        } else {
            *(uint2*)(WoH + i) = u;
        }
    }
}

// ---------------------------------------------------------------------------
// Pipelined fp16 mma.sync GEMM, templated tile width:
//   TN=128 (QKV; grid already multi-wave -> max A-reuse, 4.0 MMA/ldsm)
//   TN=64  (out-proj; small grid -> more CTAs, 4 CTAs/SM)
// 128 threads (4 warps, 2(M) x 2(N)). Double-buffered cp.async (BK=64).
// EPI 0: fp32 + bias (final). EPI 1: fp16 head-split QKV (Q scaled).
// ---------------------------------------------------------------------------
template<int TN, int EPI>
__global__ __launch_bounds__(128, (TN == 64) ? 4 : 3)
void gemm_h(const __half* __restrict__ A, const __half* __restrict__ W,
            const float* __restrict__ bias, void* __restrict__ Cv,
            int Kd, int lda, int ldb, int ldc)
{
    constexpr int LDA_ = 72;
    constexpr int LDB_ = (TN == 64) ? 72 : 136;
    constexpr int ASZ  = 128 * LDA_;
    constexpr int BSZ  = 64 * LDB_;
    constexpr int WNW  = TN / 2;             // warp-tile N width
    constexpr int NPQ  = TN / 32;            // np loop count (16-col groups/warp)
    constexpr int BCH  = TN / 8;             // B 16B-chunks per k-row

    extern __shared__ __half smh[];
    __half* As = smh;
    __half* Bs = smh + 2 * ASZ;
    const uint32_t sbA = smem_u32(As);
    const uint32_t sbB = smem_u32(Bs);

    const int tid  = threadIdx.x;            // 0..127
    const int wid  = tid >> 5;               // 0..3
    const int lane = tid & 31;
    const int gidx = lane >> 2;
    const int ctig = lane & 3;
    const int bn = blockIdx.x * TN;
    const int bm = blockIdx.y * 128;

    const int warp_n = (wid & 1) * WNW;
    const int warp_m = (wid >> 1) * 64;

    float acc[4][2 * NPQ][4];
#pragma unroll
    for (int mf = 0; mf < 4; mf++)
#pragma unroll
        for (int nf = 0; nf < 2 * NPQ; nf++)
#pragma unroll
            for (int q = 0; q < 4; q++) acc[mf][nf][q] = 0.f;

    const int nk = Kd >> 6;                  // BK = 64

    auto issue = [&](int it, int buf) {
        const int kt = it << 6;
#pragma unroll
        for (int j = 0; j < 8; j++) {        // A: 128 rows x 8 chunks = 1024
            const int seg = j * 128 + tid;
            const int r = seg >> 3, c = seg & 7;
            CP_ASYNC16(sbA + (uint32_t)(buf * ASZ + r * LDA_ + c * 8) * 2,
                       A + (size_t)(bm + r) * lda + kt + c * 8);
        }
#pragma unroll
        for (int j = 0; j < BCH / 2; j++) {  // B: 64 k-rows x BCH chunks
            const int seg = j * 128 + tid;
            const int r = seg / BCH, c = seg % BCH;
            CP_ASYNC16(sbB + (uint32_t)(buf * BSZ + r * LDB_ + c * 8) * 2,
                       W + (size_t)(kt + r) * ldb + bn + c * 8);
        }
        CP_COMMIT();
    };

    issue(0, 0);

    const int arow = lane & 15;
    const int acol = (lane >> 4) << 3;
    const int vrow = ((lane >> 3) & 1) * 8 + (lane & 7);
    const int vcol = (lane >> 4) << 3;

    for (int i = 0; i < nk; i++) {
        const int buf = i & 1;
        if (i + 1 < nk) { issue(i + 1, buf ^ 1); CP_WAIT1(); }
        else            { CP_WAIT0(); }
        __syncthreads();

        const uint32_t Ab = sbA + (uint32_t)(buf * ASZ) * 2;
        const uint32_t Bb = sbB + (uint32_t)(buf * BSZ) * 2;

#pragma unroll
        for (int ks = 0; ks < 4; ks++) {
            uint32_t afr[4][4];
#pragma unroll
            for (int mf = 0; mf < 4; mf++)
                ldsm4(afr[mf], Ab + (uint32_t)((warp_m + mf * 16 + arow) * LDA_
                                               + ks * 16 + acol) * 2);
#pragma unroll
            for (int np = 0; np < NPQ; np++) {
                uint32_t bfr[4];
                ldsm4t(bfr, Bb + (uint32_t)((ks * 16 + vrow) * LDB_
                                            + warp_n + np * 16 + vcol) * 2);
#pragma unroll
                for (int mf = 0; mf < 4; mf++) {
                    mma_f16(acc[mf][2 * np],     afr[mf], bfr[0], bfr[1]);
                    mma_f16(acc[mf][2 * np + 1], afr[mf], bfr[2], bfr[3]);
                }
            }
        }
        __syncthreads();
    }

#pragma unroll
    for (int mf = 0; mf < 4; mf++) {
#pragma unroll
        for (int nf = 0; nf < 2 * NPQ; nf++) {
            const int row0 = bm + warp_m + mf * 16 + gidx;
            const int cl   = warp_n + nf * 8 + ctig * 2;
            if (EPI == 1) {
                __half* C = (__half*)Cv;
                const int mat = bn / DOUT;
                const float sc = (mat == 0) ? 0.125f * 1.44269504f : 1.f;
                const int cg  = bn + cl - mat * DOUT;
                const int h_  = cg >> 6, hd_ = cg & 63;
                const int b_  = row0 >> 11, t_ = row0 & (TT - 1);
                __half* d0 = C + (size_t)mat * QKVSZ
                           + (((size_t)(b_ * NH + h_) << 11) + t_) * HD + hd_;
                __half* d1 = d0 + 8 * HD;
                *(uint32_t*)d0 = packh2(acc[mf][nf][0] * sc, acc[mf][nf][1] * sc);
                *(uint32_t*)d1 = packh2(acc[mf][nf][2] * sc, acc[mf][nf][3] * sc);
            } else {
                float* C = (float*)Cv;
                float* d0 = C + (size_t)row0 * ldc + bn + cl;
                float* d1 = d0 + (size_t)8 * ldc;
                float b0 = 0.f, b1 = 0.f;
                if (bias) { b0 = bias[bn + cl]; b1 = bias[bn + cl + 1]; }
                *(float2*)d0 = make_float2(acc[mf][nf][0] + b0, acc[mf][nf][1] + b1);
                *(float2*)d1 = make_float2(acc[mf][nf][2] + b0, acc[mf][nf][3] + b1);
            }
        }
    }
}

// ---------------------------------------------------------------------------
// Fused flash attention v9 (R15 form, locked): 128 threads, 32 q-rows/warp,
// fp16-accum S, in-place ex2, single ones-MMA per mf for l (pre-summed via
// shallow HADD2 on the fma pipe), 3-stage cp.async, 1 barrier per key block.
// ---------------------------------------------------------------------------
__global__ __launch_bounds__(128, 3)
void flash_attn(const __half* __restrict__ Q, const __half* __restrict__ K,
                const __half* __restrict__ V, __half* __restrict__ ctx)
{
    constexpr int LDH = 72;
    constexpr int QSZ = 128 * LDH;
    constexpr int KSZ = 64 * LDH;
    constexpr uint32_t ONES = 0x3C003C00u;  // half2(1, 1)

    extern __shared__ __half smh[];
    __half* Qs = smh;                        // 128 x 72
    __half* Ks = smh + QSZ;                  // [3][64][72]
    __half* Vs = Ks + 3 * KSZ;               // [3][64][72]
    const uint32_t sbQ = smem_u32(Qs);
    const uint32_t sbK = smem_u32(Ks);
    const uint32_t sbV = smem_u32(Vs);

    const int tid  = threadIdx.x;            // 0..127
    const int wid  = tid >> 5;               // 0..3
    const int lane = tid & 31;
    const int gidx = lane >> 2;
    const int ctig = lane & 3;
    const int q0 = blockIdx.x * 128;
    const int bh = blockIdx.y;
    const int warp_m = wid * 32;             // 32 q-rows per warp

    const __half* Qb = Q + ((size_t)bh * TT + q0) * HD;
    const __half* Kb = K + (size_t)bh * TT * HD;
    const __half* Vb = V + (size_t)bh * TT * HD;

    // stage Q
#pragma unroll
    for (int j = 0; j < 8; j++) {
        const int seg = j * 128 + tid;
        const int r = seg >> 3, c = seg & 7;
        *(uint4*)(Qs + r * LDH + c * 8) = *(const uint4*)(Qb + r * HD + c * 8);
    }

    const int arow = lane & 15;
    const int acol = (lane >> 4) << 3;
    const int brow = ((lane >> 4) << 3) + (lane & 7);
    const int bcol = ((lane >> 3) & 1) * 8;
    const int vrow = ((lane >> 3) & 1) * 8 + (lane & 7);
    const int vcol = (lane >> 4) << 3;

    auto issueKV = [&](int blk, int buf) {
        const __half* kp = Kb + (size_t)blk * 64 * HD;
        const __half* vp = Vb + (size_t)blk * 64 * HD;
#pragma unroll
        for (int j = 0; j < 4; j++) {
            const int seg = j * 128 + tid;
            const int r = seg >> 3, c = seg & 7;
            CP_ASYNC16(sbK + (uint32_t)(buf * KSZ + r * LDH + c * 8) * 2,
                       kp + r * HD + c * 8);
        }
#pragma unroll
        for (int j = 0; j < 4; j++) {
            const int seg = j * 128 + tid;
            const int r = seg >> 3, c = seg & 7;
            CP_ASYNC16(sbV + (uint32_t)(buf * KSZ + r * LDH + c * 8) * 2,
                       vp + r * HD + c * 8);
        }
        CP_COMMIT();
    };

    issueKV(0, 0);
    issueKV(1, 1);
    __syncthreads();                         // Q staged (overlaps KV issue)

    uint32_t qf[2][4][4];
#pragma unroll
    for (int mf = 0; mf < 2; mf++)
#pragma unroll
        for (int ks = 0; ks < 4; ks++)
            ldsm4(qf[mf][ks], sbQ + (uint32_t)((warp_m + mf * 16 + arow) * LDH
                                               + ks * 16 + acol) * 2);

    float O[2][8][4];
#pragma unroll
    for (int mf = 0; mf < 2; mf++)
#pragma unroll
        for (int nf = 0; nf < 8; nf++)
#pragma unroll
            for (int q = 0; q < 4; q++) O[mf][nf][q] = 0.f;
    float lacc[2][4] = {{0.f, 0.f, 0.f, 0.f}, {0.f, 0.f, 0.f, 0.f}};

    constexpr int NB = TT / 64;              // 32
    int buf = 0;

    for (int i = 0; i < NB; i++) {
        if (i + 1 < NB) CP_WAIT1();
        else            CP_WAIT0();
        __syncthreads();                     // publish stage i; prev compute done

        const uint32_t Kt = sbK + (uint32_t)(buf * KSZ) * 2;
        const uint32_t Vt = sbV + (uint32_t)(buf * KSZ) * 2;

        // ---- S' = (Q * 0.125*log2e) @ K^T, fp16 accum; kf reused by both mf ----
        uint32_t ph[2][8][2];
#pragma unroll
        for (int mf = 0; mf < 2; mf++)
#pragma unroll
            for (int nf = 0; nf < 8; nf++) { ph[mf][nf][0] = 0u; ph[mf][nf][1] = 0u; }

#pragma unroll
        for (int ks = 0; ks < 4; ks++) {
#pragma unroll
            for (int np = 0; np < 4; np++) {
                uint32_t kf[4];
                ldsm4(kf, Kt + (uint32_t)((np * 16 + brow) * LDH + ks * 16 + bcol) * 2);
#pragma unroll
                for (int mf = 0; mf < 2; mf++) {
                    mma_f16c16(ph[mf][2 * np],     qf[mf][ks], kf[0], kf[1]);
                    mma_f16c16(ph[mf][2 * np + 1], qf[mf][ks], kf[2], kf[3]);
                }
            }
        }

        // ---- P = exp2(S') in place ----
#pragma unroll
        for (int mf = 0; mf < 2; mf++)
#pragma unroll
            for (int nf = 0; nf < 8; nf++) {
                ph[mf][nf][0] = h2ex2(ph[mf][nf][0]);
                ph[mf][nf][1] = h2ex2(ph[mf][nf][1]);
            }

        // ---- l: pre-sum P fragments over 4 k-groups, ONE ones-MMA per mf ----
#pragma unroll
        for (int mf = 0; mf < 2; mf++) {
            uint32_t ls[4];
            ls[0] = hadd2u(hadd2u(ph[mf][0][0], ph[mf][2][0]),
                           hadd2u(ph[mf][4][0], ph[mf][6][0]));
            ls[1] = hadd2u(hadd2u(ph[mf][0][1], ph[mf][2][1]),
                           hadd2u(ph[mf][4][1], ph[mf][6][1]));
            ls[2] = hadd2u(hadd2u(ph[mf][1][0], ph[mf][3][0]),
                           hadd2u(ph[mf][5][0], ph[mf][7][0]));
            ls[3] = hadd2u(hadd2u(ph[mf][1][1], ph[mf][3][1]),
                           hadd2u(ph[mf][5][1], ph[mf][7][1]));
            mma_f16(lacc[mf], ls, ONES, ONES);
        }

        // ---- O += P @ V ; vf reused by both mf ----
#pragma unroll
        for (int j = 0; j < 4; j++) {
            uint32_t af[2][4];
#pragma unroll
            for (int mf = 0; mf < 2; mf++) {
                af[mf][0] = ph[mf][2 * j][0];
                af[mf][1] = ph[mf][2 * j][1];
                af[mf][2] = ph[mf][2 * j + 1][0];
                af[mf][3] = ph[mf][2 * j + 1][1];
            }
#pragma unroll
            for (int np = 0; np < 4; np++) {
                uint32_t vf[4];
                ldsm4t(vf, Vt + (uint32_t)((j * 16 + vrow) * LDH + np * 16 + vcol) * 2);
#pragma unroll
                for (int mf = 0; mf < 2; mf++) {
                    mma_f16(O[mf][2 * np],     af[mf], vf[0], vf[1]);
                    mma_f16(O[mf][2 * np + 1], af[mf], vf[2], vf[3]);
                }
            }
        }

        if (i + 2 < NB) issueKV(i + 2, (i + 2) % 3);
        buf = (buf == 2) ? 0 : buf + 1;
    }

    // ---- epilogue ----
    const int b_ = bh / NH, h_ = bh % NH;
#pragma unroll
    for (int mf = 0; mf < 2; mf++) {
        const float i0 = 1.f / lacc[mf][0];
        const float i1 = 1.f / lacc[mf][2];
        const int r0 = q0 + warp_m + mf * 16 + gidx;
        __half* base = ctx + ((size_t)(b_ * TT) + r0) * DOUT + h_ * HD;
#pragma unroll
        for (int nf = 0; nf < 8; nf++) {
            *(uint32_t*)(base + nf * 8 + 2 * ctig) =
                packh2(O[mf][nf][0] * i0, O[mf][nf][1] * i0);
            *(uint32_t*)(base + (size_t)8 * DOUT + nf * 8 + 2 * ctig) =
                packh2(O[mf][nf][2] * i1, O[mf][nf][3] * i1);
        }
    }
}

// ---------------------------------------------------------------------------
extern "C" void kernel_launch(void* const* d_in, const int* in_sizes, int n_in,
                              void* d_out, int out_size)
{
    const float* x  = (const float*)d_in[0];
    const float* Wq = (const float*)d_in[1];
    const float* Wk = (const float*)d_in[2];
    const float* Wv = (const float*)d_in[3];
    const float* Wo = (const float*)d_in[4];
    const float* bo = (const float*)d_in[5];
    float* out = (float*)d_out;

    __half *xh, *QKV, *Cp, *Wh, *WoH;
    cudaGetSymbolAddress((void**)&xh,  g_xh);
    cudaGetSymbolAddress((void**)&QKV, g_QKV);
    cudaGetSymbolAddress((void**)&Cp,  g_ctx);
    cudaGetSymbolAddress((void**)&Wh,  g_Wh);
    cudaGetSymbolAddress((void**)&WoH, g_WoH);

    constexpr int SMG128 = (2 * 128 * 72 + 2 * 64 * 136) * 2;      // 71680 B
    constexpr int SMG64  = (2 * 128 * 72 + 2 * 64 * 72) * 2;       // 55296 B
    constexpr int SMFA   = (128 * 72 + 6 * 64 * 72) * 2;           // 73728 B
    cudaFuncSetAttribute((gemm_h<128, 1>), cudaFuncAttributeMaxDynamicSharedMemorySize, SMG128);
    cudaFuncSetAttribute((gemm_h<64, 0>),  cudaFuncAttributeMaxDynamicSharedMemorySize, SMG64);
    cudaFuncSetAttribute(flash_attn, cudaFuncAttributeMaxDynamicSharedMemorySize, SMFA);

    // merged preprocessing (x + all weights, one launch)
    preproc<<<XB + 4 * WB, 256>>>(x, Wq, Wk, Wv, Wo, xh, Wh, WoH);

    // fused QKV projection (128x128 tiles, multi-wave grid: max A-reuse)
    gemm_h<128, 1><<<dim3(3 * DOUT / 128, MROWS / 128), 128, SMG128>>>(
        xh, Wh, nullptr, QKV, DIN, DIN, 3 * DOUT, 0);

    // fused flash attention -> ctx [b,t,d] fp16
    flash_attn<<<dim3(TT / 128, BB * NH), 128, SMFA>>>(
        QKV, QKV + QKVSZ, QKV + 2 * QKVSZ, Cp);

    // output projection + bias (128x64 tiles, small grid: more CTAs in flight)
    gemm_h<64, 0><<<dim3(DOUT / 64, MROWS / 128), 128, SMG64>>>(
        Cp, WoH, bo, out, DOUT, DOUT, DOUT, DOUT);
}